// round 9
// baseline (speedup 1.0000x reference)
#include <cuda_runtime.h>
#include <cuda_bf16.h>
#include <math.h>
#include <stdint.h>

#define BATCH    512
#define NCLS     100000
#define DIM      512
#define CM       64                 /* classes per tile */
#define TILES    1563               /* ceil(NCLS/64) */
#define HB       256                /* batch rows per CTA (half) */
#define STRIPS   74                 /* CTAs per half -> 148 total, one wave */
#define S_SCALE  30.0f
#define SHIFT    30.0f
#define N_U      110.0f
#define N_L      10.0f
#define M_U      1.0f
#define M_L      0.1f
#define LAMBDA_G 35.0f
#define PI_F     3.14159265358979323846f
#define WSC      64.0f              /* W pre-scale before e4m3 */

#define PITCH    528                /* smem row pitch bytes (512+16) */
#define WBUF     (CM * PITCH)       /* 33792 per W buffer */

/* dynamic smem layout (bytes) */
#define OFF_SX    0                         /* 256 x 528 = 135168 */
#define OFF_SW    135168                    /* 2 x 64 x 528 = 67584 */
#define OFF_INVN  202752                    /* float[2][64] = 512 */
#define OFF_RSUM  203264                    /* float[2][256] = 2048 */
#define OFF_RMAX  205312                    /* ull[2][256]   = 4096 */
#define OFF_LAB   209408                    /* int[256]      = 1024 */
#define OFF_TL    210432                    /* float[256]    = 1024 */
#define SMEM_BYTES 211456

// ---------------- static device scratch ----------------
__device__ uint8_t g_xq[BATCH * DIM];         // x-hat e4m3
__device__ float   g_xnf[BATCH * DIM];        // x-hat fp32 (exact target dot)
__device__ float4  g_mp[BATCH];
__device__ float   g_xnorm_cl[BATCH];
__device__ float   g_tlogit[BATCH];
__device__ int     g_labels[BATCH];
__device__ float   g_sumB[BATCH];
__device__ unsigned long long g_maxB[BATCH];

__device__ __forceinline__ unsigned int fenc(float f) {
    unsigned int u = __float_as_uint(f);
    return (u & 0x80000000u) ? ~u : (u | 0x80000000u);
}
__device__ __forceinline__ unsigned short cvt_e4m3x2(float hi, float lo) {
    unsigned short r;
    asm("cvt.rn.satfinite.e4m3x2.f32 %0, %1, %2;" : "=h"(r) : "f"(hi), "f"(lo));
    return r;
}
__device__ __forceinline__ void cpa16(uint32_t dst, const void* src) {
    asm volatile("cp.async.cg.shared.global [%0], [%1], 16;" :: "r"(dst), "l"(src));
}
__device__ __forceinline__ void ldsm_x4(uint32_t addr, unsigned& r0, unsigned& r1,
                                        unsigned& r2, unsigned& r3) {
    asm volatile("ldmatrix.sync.aligned.m8n8.x4.shared.b16 {%0,%1,%2,%3}, [%4];"
                 : "=r"(r0), "=r"(r1), "=r"(r2), "=r"(r3) : "r"(addr));
}

// ---------------- labels (+ per-call accumulator zeroing) ----------------
__global__ void k_labels(const void* lab) {
    __shared__ int s_is64;
    int tid = threadIdx.x;
    if (tid == 0) s_is64 = 1;
    __syncthreads();
    if (tid < BATCH / 2) {
        long long v = ((const long long*)lab)[tid];
        if (v < 0 || v >= (long long)NCLS) s_is64 = 0;
    }
    __syncthreads();
    if (tid < BATCH) {
        int v;
        if (s_is64) v = (int)((const long long*)lab)[tid];
        else        v = ((const int*)lab)[tid];
        g_labels[tid] = v;
        g_sumB[tid] = 0.0f;
        g_maxB[tid] = 0ull;
    }
}

// ---------------- x: norms, margin params, fp32 + fp8 normalize ----------------
__global__ void k_prep_x(const float* __restrict__ x) {
    int row = blockIdx.x;
    int t = threadIdx.x;  // 128
    float4 v = ((const float4*)(x + (size_t)row * DIM))[t];
    float ss = v.x * v.x + v.y * v.y + v.z * v.z + v.w * v.w;
    #pragma unroll
    for (int o = 16; o; o >>= 1) ss += __shfl_xor_sync(0xffffffffu, ss, o);
    __shared__ float s[4];
    if ((t & 31) == 0) s[t >> 5] = ss;
    __syncthreads();
    float tot = s[0] + s[1] + s[2] + s[3];
    float nrm = sqrtf(tot);
    float inv = 1.0f / nrm;
    if (t == 0) {
        float a = fminf(fmaxf(nrm, N_L), N_U);
        float m = (M_U - M_L) / (N_U - N_L) * (a - N_L) + M_L;
        g_mp[row] = make_float4(cosf(m), sinf(m), cosf(PI_F - m), sinf(PI_F - m) * m);
        g_xnorm_cl[row] = a;
    }
    float f0 = v.x * inv, f1 = v.y * inv, f2 = v.z * inv, f3 = v.w * inv;
    ((float4*)(g_xnf + (size_t)row * DIM))[t] = make_float4(f0, f1, f2, f3);
    unsigned short lo = cvt_e4m3x2(f1, f0);
    unsigned short hi = cvt_e4m3x2(f3, f2);
    ((uint32_t*)(g_xq + (size_t)row * DIM))[t] = (uint32_t)lo | ((uint32_t)hi << 16);
}

// ---------------- exact fp32 target-class logit ----------------
__global__ void k_target(const float* __restrict__ W) {
    int b = blockIdx.x;
    int t = threadIdx.x;  // 128
    int lab = g_labels[b];
    float4 wv = ((const float4*)(W + (size_t)lab * DIM))[t];
    float4 xv = ((const float4*)(g_xnf + (size_t)b * DIM))[t];
    float dot = wv.x * xv.x + wv.y * xv.y + wv.z * xv.z + wv.w * xv.w;
    float ssq = wv.x * wv.x + wv.y * wv.y + wv.z * wv.z + wv.w * wv.w;
    #pragma unroll
    for (int o = 16; o; o >>= 1) {
        dot += __shfl_xor_sync(0xffffffffu, dot, o);
        ssq += __shfl_xor_sync(0xffffffffu, ssq, o);
    }
    __shared__ float sd[4], sq[4];
    if ((t & 31) == 0) { sd[t >> 5] = dot; sq[t >> 5] = ssq; }
    __syncthreads();
    if (t == 0) {
        float d = sd[0] + sd[1] + sd[2] + sd[3];
        float q = sq[0] + sq[1] + sq[2] + sq[3];
        float cs = d * rsqrtf(q);
        float4 mp = g_mp[b];
        float sine = sqrtf(fmaxf(0.0f, 1.0f - cs * cs));
        float phi = cs * mp.x - sine * mp.y;
        g_tlogit[b] = ((cs - mp.z > 0.0f) ? phi : (cs - mp.w)) * S_SCALE;
    }
}

// ---------------- persistent-strip FP8 GEMM, x-hat resident, W converted in-flight ----------------
// Grid (74, 2). CTA: x-hat half (256x512 fp8) resident; ~21 class tiles of 64.
// W streamed fp32 from HBM one tile ahead: LDG -> x64 scale -> ssq -> e4m3 -> STS,
// interleaved with the current tile's MMAs (rides idle ALU/LSU under tensor-bound loop).
__global__ void __launch_bounds__(512, 1) k_gemm(const float* __restrict__ W) {
    extern __shared__ char smem[];
    uint32_t sbase = (uint32_t)__cvta_generic_to_shared(smem);
    uint32_t sx_u = sbase + OFF_SX;
    uint32_t sw_u = sbase + OFF_SW;
    float* s_invn = (float*)(smem + OFF_INVN);            // [2][64]
    float* s_rsum = (float*)(smem + OFF_RSUM);
    unsigned long long* s_rmax = (unsigned long long*)(smem + OFF_RMAX);
    int* s_lab = (int*)(smem + OFF_LAB);
    float* s_tl = (float*)(smem + OFF_TL);

    int tid = threadIdx.x;
    int strip = blockIdx.x, half = blockIdx.y;
    int hbase = half * HB;

    if (tid < HB) {
        s_lab[tid] = g_labels[hbase + tid];
        s_tl[tid] = g_tlogit[hbase + tid];
    }

    // ---- resident x-hat load ----
    #pragma unroll
    for (int j = 0; j < 16; j++) {
        int idx = tid + j * 512;
        int r = idx >> 5, ch = idx & 31;
        cpa16(sx_u + (uint32_t)(r * PITCH + ch * 16),
              g_xq + (size_t)(hbase + r) * DIM + ch * 16);
    }
    asm volatile("cp.async.commit_group;");

    // W staging geometry: 8 threads per class row; each stages 16 floats of a chunk
    int wrow = tid >> 3, och = tid & 7;                   // wrow 0..63, och 0..7

    // ---- prologue: stage tile 'strip' into buf 0 (fp32 -> e4m3) ----
    {
        int row = strip * CM + wrow;
        const float* wp = W + (size_t)((row < NCLS) ? row : 0) * DIM + och * 16;
        float ssq = 0.0f;
        #pragma unroll
        for (int c = 0; c < 4; c++) {
            const float4* src = (const float4*)(wp + c * 128);
            uint32_t h[4];
            #pragma unroll
            for (int i = 0; i < 4; i++) {
                float4 v = src[i];
                float a = v.x * WSC, b = v.y * WSC, cc = v.z * WSC, d = v.w * WSC;
                ssq += a * a + b * b + cc * cc + d * d;
                unsigned short lo = cvt_e4m3x2(b, a);
                unsigned short hi = cvt_e4m3x2(d, cc);
                h[i] = (uint32_t)lo | ((uint32_t)hi << 16);
            }
            *(uint4*)(smem + OFF_SW + wrow * PITCH + c * 128 + och * 16) =
                make_uint4(h[0], h[1], h[2], h[3]);
        }
        ssq += __shfl_xor_sync(0xffffffffu, ssq, 1);
        ssq += __shfl_xor_sync(0xffffffffu, ssq, 2);
        ssq += __shfl_xor_sync(0xffffffffu, ssq, 4);
        if (och == 0) s_invn[wrow] = (ssq > 0.f) ? rsqrtf(ssq) : 0.f;
    }
    asm volatile("cp.async.wait_group 0;" ::: "memory");
    __syncthreads();

    int warp = tid >> 5, lane = tid & 31;
    int wm = warp & 1;        // M half (0..1) of 64 classes
    int wn = warp >> 1;       // N eighth (0..7) of 256 batch
    int g = lane >> 2, tg = lane & 3;

    int a_lrow = wm * 32 + (lane & 7) + ((lane >> 3) & 1) * 8;
    int a_lkb  = (lane >> 4) * 16;
    int b_lrow = wn * 32 + (lane & 7) + (lane >> 4) * 8;
    int b_lkb  = ((lane >> 3) & 1) * 16;

    int cur = 0;
    #pragma unroll 1
    for (int t = strip; t < TILES; t += STRIPS) {
        int tn = t + STRIPS;
        bool stage = (tn < TILES);
        int nxt = cur ^ 1;
        const float* wpn = nullptr;
        if (stage) {
            int row = tn * CM + wrow;
            wpn = W + (size_t)((row < NCLS) ? row : 0) * DIM + och * 16;
        }
        float ssq = 0.0f;

        float acc[2][4][4];
        #pragma unroll
        for (int mt = 0; mt < 2; mt++)
            #pragma unroll
            for (int nt = 0; nt < 4; nt++)
                #pragma unroll
                for (int e = 0; e < 4; e++) acc[mt][nt][e] = 0.0f;

        uint32_t Abase = sw_u + (uint32_t)(cur * WBUF);
        #pragma unroll
        for (int c = 0; c < 4; c++) {
            // stage chunk c of next tile (LDG latency hidden under this chunk's MMAs)
            if (stage) {
                const float4* src = (const float4*)(wpn + c * 128);
                uint32_t h[4];
                #pragma unroll
                for (int i = 0; i < 4; i++) {
                    float4 v = src[i];
                    float a = v.x * WSC, b = v.y * WSC, cc = v.z * WSC, d = v.w * WSC;
                    ssq += a * a + b * b + cc * cc + d * d;
                    unsigned short lo = cvt_e4m3x2(b, a);
                    unsigned short hi = cvt_e4m3x2(d, cc);
                    h[i] = (uint32_t)lo | ((uint32_t)hi << 16);
                }
                *(uint4*)(smem + OFF_SW + nxt * WBUF + wrow * PITCH + c * 128 + och * 16) =
                    make_uint4(h[0], h[1], h[2], h[3]);
            }
            #pragma unroll
            for (int ks = 0; ks < 4; ks++) {
                int kb = c * 128 + ks * 32;
                unsigned af[2][4];
                #pragma unroll
                for (int mt = 0; mt < 2; mt++)
                    ldsm_x4(Abase + (uint32_t)((a_lrow + mt * 16) * PITCH + kb + a_lkb),
                            af[mt][0], af[mt][1], af[mt][2], af[mt][3]);
                #pragma unroll
                for (int p = 0; p < 2; p++) {
                    unsigned b0, b1, b2, b3;
                    ldsm_x4(sx_u + (uint32_t)((b_lrow + p * 16) * PITCH + kb + b_lkb),
                            b0, b1, b2, b3);
                    #pragma unroll
                    for (int mt = 0; mt < 2; mt++) {
                        asm volatile(
                            "mma.sync.aligned.m16n8k32.row.col.f32.e4m3.e4m3.f32 "
                            "{%0,%1,%2,%3},{%4,%5,%6,%7},{%8,%9},{%0,%1,%2,%3};\n"
                            : "+f"(acc[mt][2 * p][0]), "+f"(acc[mt][2 * p][1]),
                              "+f"(acc[mt][2 * p][2]), "+f"(acc[mt][2 * p][3])
                            : "r"(af[mt][0]), "r"(af[mt][1]), "r"(af[mt][2]), "r"(af[mt][3]),
                              "r"(b0), "r"(b1));
                        asm volatile(
                            "mma.sync.aligned.m16n8k32.row.col.f32.e4m3.e4m3.f32 "
                            "{%0,%1,%2,%3},{%4,%5,%6,%7},{%8,%9},{%0,%1,%2,%3};\n"
                            : "+f"(acc[mt][2 * p + 1][0]), "+f"(acc[mt][2 * p + 1][1]),
                              "+f"(acc[mt][2 * p + 1][2]), "+f"(acc[mt][2 * p + 1][3])
                            : "r"(af[mt][0]), "r"(af[mt][1]), "r"(af[mt][2]), "r"(af[mt][3]),
                              "r"(b2), "r"(b3));
                    }
                }
            }
        }

        if (stage) {
            ssq += __shfl_xor_sync(0xffffffffu, ssq, 1);
            ssq += __shfl_xor_sync(0xffffffffu, ssq, 2);
            ssq += __shfl_xor_sync(0xffffffffu, ssq, 4);
            if (och == 0) s_invn[nxt * 64 + wrow] = (ssq > 0.f) ? rsqrtf(ssq) : 0.f;
        }

        // ---- tile epilogue (invn from this tile's buffer) ----
        float invn_r[2][2];
        #pragma unroll
        for (int mt = 0; mt < 2; mt++)
            #pragma unroll
            for (int hi = 0; hi < 2; hi++)
                invn_r[mt][hi] = s_invn[cur * 64 + wm * 32 + mt * 16 + g + hi * 8];

        #pragma unroll
        for (int nt = 0; nt < 4; nt++) {
            #pragma unroll
            for (int lo = 0; lo < 2; lo++) {
                int lcol = wn * 32 + nt * 8 + 2 * tg + lo;     // 0..255
                int lab = s_lab[lcol];
                float tl = s_tl[lcol];
                float lsum = 0.0f;
                unsigned long long lmax = 0ull;
                #pragma unroll
                for (int mt = 0; mt < 2; mt++) {
                    #pragma unroll
                    for (int hi = 0; hi < 2; hi++) {
                        int ccls = t * CM + wm * 32 + mt * 16 + g + hi * 8;
                        if (ccls < NCLS) {
                            float v = acc[mt][nt][hi * 2 + lo] * invn_r[mt][hi];
                            float logit = (ccls == lab) ? tl : v * S_SCALE;
                            lsum += __expf(logit - SHIFT);
                            unsigned long long pk =
                                ((unsigned long long)fenc(logit) << 32) |
                                (unsigned long long)(0xFFFFFFFFu - (unsigned)ccls);
                            lmax = (pk > lmax) ? pk : lmax;
                        }
                    }
                }
                #pragma unroll
                for (int off = 4; off < 32; off <<= 1) {
                    lsum += __shfl_xor_sync(0xffffffffu, lsum, off);
                    unsigned long long o = __shfl_xor_sync(0xffffffffu, lmax, off);
                    lmax = (o > lmax) ? o : lmax;
                }
                if (g == 0) {
                    s_rsum[wm * HB + lcol] = lsum;
                    s_rmax[wm * HB + lcol] = lmax;
                }
            }
        }
        __syncthreads();
        if (tid < HB) {
            atomicAdd(&g_sumB[hbase + tid], s_rsum[tid] + s_rsum[HB + tid]);
            unsigned long long a = s_rmax[tid], b = s_rmax[HB + tid];
            atomicMax(&g_maxB[hbase + tid], (a > b) ? a : b);
        }
        __syncthreads();
        cur ^= 1;
    }
}

// ---------------- final scalar outputs ----------------
__global__ void k_final(float* __restrict__ out, int out_size) {
    int b = threadIdx.x;  // 512
    float lse = logf(g_sumB[b]) + SHIFT;
    float ce = lse - g_tlogit[b];
    int pred = (int)(0xFFFFFFFFu - (unsigned)(g_maxB[b] & 0xFFFFFFFFull));
    float corr = (pred == g_labels[b]) ? 1.0f : 0.0f;
    float a = g_xnorm_cl[b];
    float gt = a / (N_U * N_U) + 1.0f / a;

    __shared__ float s1[512], s2[512], s3[512];
    s1[b] = ce; s2[b] = corr; s3[b] = gt;
    __syncthreads();
    for (int o = 256; o; o >>= 1) {
        if (b < o) { s1[b] += s1[b + o]; s2[b] += s2[b + o]; s3[b] += s3[b + o]; }
        __syncthreads();
    }
    if (b == 0) {
        float loss = s1[0] / (float)BATCH + LAMBDA_G * (s3[0] / (float)BATCH);
        if (out_size >= 1) out[0] = loss;
        if (out_size >= 2) out[1] = s2[0] / (float)BATCH * 100.0f;
    }
    if (b >= 2 && b < out_size) out[b] = 0.0f;
}

extern "C" void kernel_launch(void* const* d_in, const int* in_sizes, int n_in,
                              void* d_out, int out_size) {
    const float* x = (const float*)d_in[0];
    const void* lab = d_in[1];
    const float* w = (const float*)d_in[2];
    (void)in_sizes; (void)n_in;

    cudaFuncSetAttribute(k_gemm, cudaFuncAttributeMaxDynamicSharedMemorySize, SMEM_BYTES);

    k_labels<<<1, 512>>>(lab);
    k_prep_x<<<BATCH, 128>>>(x);
    k_target<<<BATCH, 128>>>(w);
    dim3 grid(STRIPS, 2);
    k_gemm<<<grid, 512, SMEM_BYTES>>>(w);
    k_final<<<1, 512>>>((float*)d_out, out_size);
}

// round 10
// speedup vs baseline: 1.2072x; 1.2072x over previous
#include <cuda_runtime.h>
#include <cuda_bf16.h>
#include <math.h>
#include <stdint.h>

#define BATCH    512
#define NCLS     100000
#define DIM      512
#define CM       64                 /* classes per tile */
#define TILES    1563               /* ceil(NCLS/64) */
#define HB       256                /* batch rows per CTA (half) */
#define STRIPS   74                 /* CTAs per half -> 148 total */
#define S_SCALE  30.0f
#define SHIFT    30.0f
#define N_U      110.0f
#define N_L      10.0f
#define M_U      1.0f
#define M_L      0.1f
#define LAMBDA_G 35.0f
#define PI_F     3.14159265358979323846f
#define WSC      64.0f              /* W pre-scale before e4m3 */
#define LOG2E    1.44269504f
#define ARG_SCALE 43.2808512f       /* 30*log2(e) */
#define ARG_BIAS  (-43.2808512f)

#define PITCH    528                /* smem row pitch bytes (512+16) */
#define WBUF     (CM * PITCH)       /* 33792 per W buffer */

/* dynamic smem layout (bytes) */
#define OFF_SX    0                         /* 256 x 528 = 135168 */
#define OFF_SW    135168                    /* 2 x 64 x 528 = 67584 */
#define OFF_INVN  202752                    /* float[2][64] = 512 */
#define OFF_LAB   203264                    /* int[256]   = 1024 */
#define OFF_AT    204288                    /* float[256] = 1024 */
#define SMEM_BYTES 205312

// ---------------- static device scratch ----------------
__device__ uint8_t  g_xq[BATCH * DIM];        // x-hat e4m3
__device__ float    g_xnf[BATCH * DIM];       // x-hat fp32 (exact target dot)
__device__ float4   g_mp[BATCH];
__device__ float    g_xnorm_cl[BATCH];
__device__ float    g_tlogit[BATCH];          // exact target logit
__device__ float    g_argt[BATCH];            // (tlogit-SHIFT)*log2e
__device__ int      g_labels[BATCH];
__device__ float    g_sumB[BATCH];
__device__ unsigned g_maxB32[BATCH];

__device__ __forceinline__ unsigned fenc(float f) {
    unsigned u = __float_as_uint(f);
    return (u & 0x80000000u) ? ~u : (u | 0x80000000u);
}
__device__ __forceinline__ float ex2(float x) {
    float r;
    asm("ex2.approx.ftz.f32 %0, %1;" : "=f"(r) : "f"(x));
    return r;
}
__device__ __forceinline__ unsigned short cvt_e4m3x2(float hi, float lo) {
    unsigned short r;
    asm("cvt.rn.satfinite.e4m3x2.f32 %0, %1, %2;" : "=h"(r) : "f"(hi), "f"(lo));
    return r;
}
__device__ __forceinline__ void cpa16(uint32_t dst, const void* src) {
    asm volatile("cp.async.cg.shared.global [%0], [%1], 16;" :: "r"(dst), "l"(src));
}
__device__ __forceinline__ void ldsm_x4(uint32_t addr, unsigned& r0, unsigned& r1,
                                        unsigned& r2, unsigned& r3) {
    asm volatile("ldmatrix.sync.aligned.m8n8.x4.shared.b16 {%0,%1,%2,%3}, [%4];"
                 : "=r"(r0), "=r"(r1), "=r"(r2), "=r"(r3) : "r"(addr));
}

// ---------------- labels (+ per-call accumulator zeroing) ----------------
__global__ void k_labels(const void* lab) {
    __shared__ int s_is64;
    int tid = threadIdx.x;
    if (tid == 0) s_is64 = 1;
    __syncthreads();
    if (tid < BATCH / 2) {
        long long v = ((const long long*)lab)[tid];
        if (v < 0 || v >= (long long)NCLS) s_is64 = 0;
    }
    __syncthreads();
    if (tid < BATCH) {
        int v;
        if (s_is64) v = (int)((const long long*)lab)[tid];
        else        v = ((const int*)lab)[tid];
        g_labels[tid] = v;
        g_sumB[tid] = 0.0f;
        g_maxB32[tid] = 0u;
    }
}

// ---------------- x: norms, margin params, fp32 + fp8 normalize ----------------
__global__ void k_prep_x(const float* __restrict__ x) {
    int row = blockIdx.x;
    int t = threadIdx.x;  // 128
    float4 v = ((const float4*)(x + (size_t)row * DIM))[t];
    float ss = v.x * v.x + v.y * v.y + v.z * v.z + v.w * v.w;
    #pragma unroll
    for (int o = 16; o; o >>= 1) ss += __shfl_xor_sync(0xffffffffu, ss, o);
    __shared__ float s[4];
    if ((t & 31) == 0) s[t >> 5] = ss;
    __syncthreads();
    float tot = s[0] + s[1] + s[2] + s[3];
    float nrm = sqrtf(tot);
    float inv = 1.0f / nrm;
    if (t == 0) {
        float a = fminf(fmaxf(nrm, N_L), N_U);
        float m = (M_U - M_L) / (N_U - N_L) * (a - N_L) + M_L;
        g_mp[row] = make_float4(cosf(m), sinf(m), cosf(PI_F - m), sinf(PI_F - m) * m);
        g_xnorm_cl[row] = a;
    }
    float f0 = v.x * inv, f1 = v.y * inv, f2 = v.z * inv, f3 = v.w * inv;
    ((float4*)(g_xnf + (size_t)row * DIM))[t] = make_float4(f0, f1, f2, f3);
    unsigned short lo = cvt_e4m3x2(f1, f0);
    unsigned short hi = cvt_e4m3x2(f3, f2);
    ((uint32_t*)(g_xq + (size_t)row * DIM))[t] = (uint32_t)lo | ((uint32_t)hi << 16);
}

// ---------------- exact fp32 target-class logit ----------------
__global__ void k_target(const float* __restrict__ W) {
    int b = blockIdx.x;
    int t = threadIdx.x;  // 128
    int lab = g_labels[b];
    float4 wv = ((const float4*)(W + (size_t)lab * DIM))[t];
    float4 xv = ((const float4*)(g_xnf + (size_t)b * DIM))[t];
    float dot = wv.x * xv.x + wv.y * xv.y + wv.z * xv.z + wv.w * xv.w;
    float ssq = wv.x * wv.x + wv.y * wv.y + wv.z * wv.z + wv.w * wv.w;
    #pragma unroll
    for (int o = 16; o; o >>= 1) {
        dot += __shfl_xor_sync(0xffffffffu, dot, o);
        ssq += __shfl_xor_sync(0xffffffffu, ssq, o);
    }
    __shared__ float sd[4], sq[4];
    if ((t & 31) == 0) { sd[t >> 5] = dot; sq[t >> 5] = ssq; }
    __syncthreads();
    if (t == 0) {
        float d = sd[0] + sd[1] + sd[2] + sd[3];
        float q = sq[0] + sq[1] + sq[2] + sq[3];
        float cs = d * rsqrtf(q);
        float4 mp = g_mp[b];
        float sine = sqrtf(fmaxf(0.0f, 1.0f - cs * cs));
        float phi = cs * mp.x - sine * mp.y;
        float tl = ((cs - mp.z > 0.0f) ? phi : (cs - mp.w)) * S_SCALE;
        g_tlogit[b] = tl;
        g_argt[b] = (tl - SHIFT) * LOG2E;
    }
}

// ---------------- persistent-strip FP8 GEMM: slim epilogue, register-resident partials ----------------
__global__ void __launch_bounds__(512, 1) k_gemm(const float* __restrict__ W) {
    extern __shared__ char smem[];
    uint32_t sbase = (uint32_t)__cvta_generic_to_shared(smem);
    uint32_t sx_u = sbase + OFF_SX;
    uint32_t sw_u = sbase + OFF_SW;
    float* s_invn = (float*)(smem + OFF_INVN);            // [2][64] = invn*ARG_SCALE
    int* s_lab = (int*)(smem + OFF_LAB);
    float* s_at = (float*)(smem + OFF_AT);

    int tid = threadIdx.x;
    int strip = blockIdx.x, half = blockIdx.y;
    int hbase = half * HB;

    if (tid < HB) {
        s_lab[tid] = g_labels[hbase + tid];
        s_at[tid]  = g_argt[hbase + tid];
    }

    // ---- resident x-hat load ----
    #pragma unroll
    for (int j = 0; j < 16; j++) {
        int idx = tid + j * 512;
        int r = idx >> 5, ch = idx & 31;
        cpa16(sx_u + (uint32_t)(r * PITCH + ch * 16),
              g_xq + (size_t)(hbase + r) * DIM + ch * 16);
    }
    asm volatile("cp.async.commit_group;");

    int wrow = tid >> 3, och = tid & 7;                   // W staging geometry

    // ---- prologue: stage tile 'strip' into buf 0 ----
    {
        int row = strip * CM + wrow;
        bool val = row < NCLS;
        const float* wp = W + (size_t)(val ? row : 0) * DIM + och * 16;
        float ssq = 0.0f;
        #pragma unroll
        for (int c = 0; c < 4; c++) {
            uint32_t h[4] = {0u, 0u, 0u, 0u};
            if (val) {
                const float4* src = (const float4*)(wp + c * 128);
                #pragma unroll
                for (int i = 0; i < 4; i++) {
                    float4 v = src[i];
                    float a = v.x * WSC, b = v.y * WSC, cc = v.z * WSC, d = v.w * WSC;
                    ssq += a * a + b * b + cc * cc + d * d;
                    unsigned short lo = cvt_e4m3x2(b, a);
                    unsigned short hi = cvt_e4m3x2(d, cc);
                    h[i] = (uint32_t)lo | ((uint32_t)hi << 16);
                }
            }
            *(uint4*)(smem + OFF_SW + wrow * PITCH + c * 128 + och * 16) =
                make_uint4(h[0], h[1], h[2], h[3]);
        }
        ssq += __shfl_xor_sync(0xffffffffu, ssq, 1);
        ssq += __shfl_xor_sync(0xffffffffu, ssq, 2);
        ssq += __shfl_xor_sync(0xffffffffu, ssq, 4);
        if (och == 0)
            s_invn[wrow] = (val && ssq > 0.f) ? rsqrtf(ssq) * ARG_SCALE : 0.f;
    }
    asm volatile("cp.async.wait_group 0;" ::: "memory");
    __syncthreads();

    int warp = tid >> 5, lane = tid & 31;
    int wm = warp & 1;        // M half (0..1) of 64 classes
    int wn = warp >> 1;       // N eighth (0..7) of 256 batch
    int g = lane >> 2, tg = lane & 3;

    int a_lrow = wm * 32 + (lane & 7) + ((lane >> 3) & 1) * 8;
    int a_lkb  = (lane >> 4) * 16;
    int b_lrow = wn * 32 + (lane & 7) + (lane >> 4) * 8;
    int b_lkb  = ((lane >> 3) & 1) * 16;

    // per-column (8 samples/thread) state, resident across all tiles
    int lab_r[8]; float argt_r[8], lsum[8], amax[8];
    #pragma unroll
    for (int nt = 0; nt < 4; nt++)
        #pragma unroll
        for (int lo = 0; lo < 2; lo++) {
            int j = nt * 2 + lo;
            int lcol = wn * 32 + nt * 8 + 2 * tg + lo;
            lab_r[j] = s_lab[lcol];
            argt_r[j] = s_at[lcol];
            lsum[j] = 0.0f;
            amax[j] = -1e30f;
        }

    int cur = 0;
    #pragma unroll 1
    for (int t = strip; t < TILES; t += STRIPS) {
        int tn = t + STRIPS;
        bool stage = (tn < TILES);
        int nxt = cur ^ 1;
        const float* wpn = nullptr;
        bool wval = false;
        if (stage) {
            int row = tn * CM + wrow;
            wval = row < NCLS;
            wpn = W + (size_t)(wval ? row : 0) * DIM + och * 16;
        }
        float ssq = 0.0f;

        float acc[2][4][4];
        #pragma unroll
        for (int mt = 0; mt < 2; mt++)
            #pragma unroll
            for (int nt = 0; nt < 4; nt++)
                #pragma unroll
                for (int e = 0; e < 4; e++) acc[mt][nt][e] = 0.0f;

        uint32_t Abase = sw_u + (uint32_t)(cur * WBUF);
        #pragma unroll
        for (int c = 0; c < 4; c++) {
            if (stage) {
                uint32_t h[4] = {0u, 0u, 0u, 0u};
                if (wval) {
                    const float4* src = (const float4*)(wpn + c * 128);
                    #pragma unroll
                    for (int i = 0; i < 4; i++) {
                        float4 v = src[i];
                        float a = v.x * WSC, b = v.y * WSC, cc = v.z * WSC, d = v.w * WSC;
                        ssq += a * a + b * b + cc * cc + d * d;
                        unsigned short lo = cvt_e4m3x2(b, a);
                        unsigned short hi = cvt_e4m3x2(d, cc);
                        h[i] = (uint32_t)lo | ((uint32_t)hi << 16);
                    }
                }
                *(uint4*)(smem + OFF_SW + nxt * WBUF + wrow * PITCH + c * 128 + och * 16) =
                    make_uint4(h[0], h[1], h[2], h[3]);
            }
            #pragma unroll
            for (int ks = 0; ks < 4; ks++) {
                int kb = c * 128 + ks * 32;
                unsigned af[2][4];
                #pragma unroll
                for (int mt = 0; mt < 2; mt++)
                    ldsm_x4(Abase + (uint32_t)((a_lrow + mt * 16) * PITCH + kb + a_lkb),
                            af[mt][0], af[mt][1], af[mt][2], af[mt][3]);
                #pragma unroll
                for (int p = 0; p < 2; p++) {
                    unsigned b0, b1, b2, b3;
                    ldsm_x4(sx_u + (uint32_t)((b_lrow + p * 16) * PITCH + kb + b_lkb),
                            b0, b1, b2, b3);
                    #pragma unroll
                    for (int mt = 0; mt < 2; mt++) {
                        asm volatile(
                            "mma.sync.aligned.m16n8k32.row.col.f32.e4m3.e4m3.f32 "
                            "{%0,%1,%2,%3},{%4,%5,%6,%7},{%8,%9},{%0,%1,%2,%3};\n"
                            : "+f"(acc[mt][2 * p][0]), "+f"(acc[mt][2 * p][1]),
                              "+f"(acc[mt][2 * p][2]), "+f"(acc[mt][2 * p][3])
                            : "r"(af[mt][0]), "r"(af[mt][1]), "r"(af[mt][2]), "r"(af[mt][3]),
                              "r"(b0), "r"(b1));
                        asm volatile(
                            "mma.sync.aligned.m16n8k32.row.col.f32.e4m3.e4m3.f32 "
                            "{%0,%1,%2,%3},{%4,%5,%6,%7},{%8,%9},{%0,%1,%2,%3};\n"
                            : "+f"(acc[mt][2 * p + 1][0]), "+f"(acc[mt][2 * p + 1][1]),
                              "+f"(acc[mt][2 * p + 1][2]), "+f"(acc[mt][2 * p + 1][3])
                            : "r"(af[mt][0]), "r"(af[mt][1]), "r"(af[mt][2]), "r"(af[mt][3]),
                              "r"(b2), "r"(b3));
                    }
                }
            }
        }

        if (stage) {
            ssq += __shfl_xor_sync(0xffffffffu, ssq, 1);
            ssq += __shfl_xor_sync(0xffffffffu, ssq, 2);
            ssq += __shfl_xor_sync(0xffffffffu, ssq, 4);
            if (och == 0)
                s_invn[nxt * 64 + wrow] = (wval && ssq > 0.f) ? rsqrtf(ssq) * ARG_SCALE : 0.f;
        }

        // ---- slim epilogue: arg = acc*invn43 + bias; exp2-sum + float max ----
        float invn43_r[2][2];
        #pragma unroll
        for (int mt = 0; mt < 2; mt++)
            #pragma unroll
            for (int hi = 0; hi < 2; hi++)
                invn43_r[mt][hi] = s_invn[cur * 64 + wm * 32 + mt * 16 + g + hi * 8];

        #pragma unroll
        for (int nt = 0; nt < 4; nt++) {
            #pragma unroll
            for (int lo = 0; lo < 2; lo++) {
                const int j = nt * 2 + lo;
                float a[4];
                #pragma unroll
                for (int mt = 0; mt < 2; mt++)
                    #pragma unroll
                    for (int hi = 0; hi < 2; hi++)
                        a[mt * 2 + hi] =
                            fmaf(acc[mt][nt][hi * 2 + lo], invn43_r[mt][hi], ARG_BIAS);
                if ((lab_r[j] >> 6) == t) {       // label lives in this tile (rare)
                    #pragma unroll
                    for (int mt = 0; mt < 2; mt++)
                        #pragma unroll
                        for (int hi = 0; hi < 2; hi++) {
                            int ccls = t * CM + wm * 32 + mt * 16 + g + hi * 8;
                            if (ccls == lab_r[j]) a[mt * 2 + hi] = argt_r[j];
                        }
                }
                #pragma unroll
                for (int e = 0; e < 4; e++) {
                    lsum[j] += ex2(a[e]);
                    amax[j] = fmaxf(amax[j], a[e]);
                }
            }
        }
        __syncthreads();
        cur ^= 1;
    }

    // ---- single end-of-kernel reduction + atomics ----
    #pragma unroll
    for (int nt = 0; nt < 4; nt++) {
        #pragma unroll
        for (int lo = 0; lo < 2; lo++) {
            const int j = nt * 2 + lo;
            float s = lsum[j], m = amax[j];
            #pragma unroll
            for (int off = 4; off < 32; off <<= 1) {
                s += __shfl_xor_sync(0xffffffffu, s, off);
                m = fmaxf(m, __shfl_xor_sync(0xffffffffu, m, off));
            }
            if (g == 0) {
                int lcol = wn * 32 + nt * 8 + 2 * tg + lo;
                atomicAdd(&g_sumB[hbase + lcol], s);
                atomicMax(&g_maxB32[hbase + lcol], fenc(m));
            }
        }
    }
}

// ---------------- final scalar outputs ----------------
__global__ void k_final(float* __restrict__ out, int out_size) {
    int b = threadIdx.x;  // 512
    // remove the 32 zero-padded class rows' exact contribution (each = 2^ARG_BIAS)
    float sum = g_sumB[b] - 32.0f * ex2(ARG_BIAS);
    float lse = logf(sum) + SHIFT;
    float ce = lse - g_tlogit[b];
    float corr = (g_maxB32[b] == fenc(g_argt[b])) ? 1.0f : 0.0f;
    float a = g_xnorm_cl[b];
    float gt = a / (N_U * N_U) + 1.0f / a;

    __shared__ float s1[512], s2[512], s3[512];
    s1[b] = ce; s2[b] = corr; s3[b] = gt;
    __syncthreads();
    for (int o = 256; o; o >>= 1) {
        if (b < o) { s1[b] += s1[b + o]; s2[b] += s2[b + o]; s3[b] += s3[b + o]; }
        __syncthreads();
    }
    if (b == 0) {
        float loss = s1[0] / (float)BATCH + LAMBDA_G * (s3[0] / (float)BATCH);
        if (out_size >= 1) out[0] = loss;
        if (out_size >= 2) out[1] = s2[0] / (float)BATCH * 100.0f;
    }
    if (b >= 2 && b < out_size) out[b] = 0.0f;
}

extern "C" void kernel_launch(void* const* d_in, const int* in_sizes, int n_in,
                              void* d_out, int out_size) {
    const float* x = (const float*)d_in[0];
    const void* lab = d_in[1];
    const float* w = (const float*)d_in[2];
    (void)in_sizes; (void)n_in;

    cudaFuncSetAttribute(k_gemm, cudaFuncAttributeMaxDynamicSharedMemorySize, SMEM_BYTES);

    k_labels<<<1, 512>>>(lab);
    k_prep_x<<<BATCH, 128>>>(x);
    k_target<<<BATCH, 128>>>(w);
    dim3 grid(STRIPS, 2);
    k_gemm<<<grid, 512, SMEM_BYTES>>>(w);
    k_final<<<1, 512>>>((float*)d_out, out_size);
}